// round 3
// baseline (speedup 1.0000x reference)
#include <cuda_runtime.h>

#define S 1024
#define G 10
#define F 5
#define BB 8
#define CC 3
#define KW (2*F+1)

// Scratch for the smoothed, clipped offset field: (B, 2, G, G)
__device__ float g_smooth_dev[BB * 2 * G * G];

// ---------------------------------------------------------------------------
// Kernel 1: 11x11 edge-padded conv of the 10x10 offset fields + clip.
// Trivial work (8*2*100 outputs x 121 taps). One block per (b, channel).
// ---------------------------------------------------------------------------
__global__ void smooth_kernel(const float* __restrict__ ox,
                              const float* __restrict__ oy,
                              const float* __restrict__ w,
                              const int*   __restrict__ mm_raw)
{
    // max_move may be int32 or float32 bits; decode defensively.
    int   mi = mm_raw[0];
    float max_move = (mi > 0 && mi < 1000000) ? (float)mi : __int_as_float(mi);
    float max_offset = 2.0f * max_move / (float)S;

    __shared__ float sw[KW * KW];
    __shared__ float so[G * G];

    int b  = blockIdx.x >> 1;
    int ch = blockIdx.x & 1;
    const float* o = (ch == 0 ? ox : oy) + b * G * G;

    for (int i = threadIdx.x; i < KW * KW; i += blockDim.x) sw[i] = w[i];
    for (int i = threadIdx.x; i < G * G;   i += blockDim.x) so[i] = o[i];
    __syncthreads();

    for (int idx = threadIdx.x; idx < G * G; idx += blockDim.x) {
        int i = idx / G, j = idx % G;
        float acc = 0.0f;
        #pragma unroll
        for (int ky = 0; ky < KW; ky++) {
            int yy = i + ky - F;
            yy = min(max(yy, 0), G - 1);
            #pragma unroll
            for (int kx = 0; kx < KW; kx++) {
                int xx = j + kx - F;
                xx = min(max(xx, 0), G - 1);
                acc += so[yy * G + xx] * sw[ky * KW + kx];
            }
        }
        acc *= max_offset;
        acc = fminf(fmaxf(acc, -max_offset), max_offset);
        g_smooth_dev[(b * 2 + ch) * G * G + idx] = acc;
    }
}

// ---------------------------------------------------------------------------
// Kernel 2: fused upsample + grid build + bilinear grid_sample for 3 channels.
// One thread per (b, y, x); x fastest for coalescing. Field in shared mem.
// ---------------------------------------------------------------------------
__global__ __launch_bounds__(256)
void deform_kernel(const float* __restrict__ x, float* __restrict__ out)
{
    const int b    = blockIdx.z;
    const int y    = blockIdx.y;
    const int xcol = blockIdx.x * blockDim.x + threadIdx.x;

    __shared__ float sg[2 * G * G];
    for (int i = threadIdx.x; i < 2 * G * G; i += blockDim.x)
        sg[i] = g_smooth_dev[b * 2 * G * G + i];
    __syncthreads();

    const float* sgx = sg;
    const float* sgy = sg + G * G;

    const float scale = (float)G / (float)S;   // 10/1024, exact

    // Row interpolation coordinates (shared across warp via blockIdx.y)
    float sy  = fmaxf(((float)y + 0.5f) * scale - 0.5f, 0.0f);
    int   iy0 = min((int)floorf(sy), G - 1);
    int   iy1 = min(iy0 + 1, G - 1);
    float wy  = sy - (float)iy0;

    // Column interpolation coordinates
    float sx  = fmaxf(((float)xcol + 0.5f) * scale - 0.5f, 0.0f);
    int   jx0 = min((int)floorf(sx), G - 1);
    int   jx1 = min(jx0 + 1, G - 1);
    float wx  = sx - (float)jx0;

    float omwy = 1.0f - wy, omwx = 1.0f - wx;

    // Bilinear sample of the 10x10 smoothed offset fields
    float gx = (sgx[iy0 * G + jx0] * omwy + sgx[iy1 * G + jx0] * wy) * omwx
             + (sgx[iy0 * G + jx1] * omwy + sgx[iy1 * G + jx1] * wy) * wx;
    float gy = (sgy[iy0 * G + jx0] * omwy + sgy[iy1 * G + jx0] * wy) * omwx
             + (sgy[iy0 * G + jx1] * omwy + sgy[iy1 * G + jx1] * wy) * wx;

    // Base identity grid: lin = i/(S-1), P = lin*2-1
    float px = (float)xcol / (float)(S - 1) * 2.0f - 1.0f;
    float py = (float)y    / (float)(S - 1) * 2.0f - 1.0f;

    float g0 = fminf(fmaxf(gx + px, -1.0f), 1.0f);   // x coordinate
    float g1 = fminf(fmaxf(gy + py, -1.0f), 1.0f);   // y coordinate

    // grid_sample source coordinates
    float ix  = ((g0 + 1.0f) * (float)S - 1.0f) * 0.5f;
    float iyf = ((g1 + 1.0f) * (float)S - 1.0f) * 0.5f;

    float fx0 = floorf(ix), fy0 = floorf(iyf);
    int x0 = (int)fx0, y0 = (int)fy0;
    int x1 = x0 + 1,   y1 = y0 + 1;
    float ax = ix - fx0, ay = iyf - fy0;
    float omax = 1.0f - ax, omay = 1.0f - ay;

    float m_x0 = (x0 >= 0 && x0 < S) ? 1.0f : 0.0f;
    float m_x1 = (x1 >= 0 && x1 < S) ? 1.0f : 0.0f;
    float m_y0 = (y0 >= 0 && y0 < S) ? 1.0f : 0.0f;
    float m_y1 = (y1 >= 0 && y1 < S) ? 1.0f : 0.0f;

    float w00 = omay * omax * (m_y0 * m_x0);
    float w01 = omay * ax   * (m_y0 * m_x1);
    float w10 = ay   * omax * (m_y1 * m_x0);
    float w11 = ay   * ax   * (m_y1 * m_x1);

    int xc0 = min(max(x0, 0), S - 1);
    int xc1 = min(max(x1, 0), S - 1);
    int yc0 = min(max(y0, 0), S - 1);
    int yc1 = min(max(y1, 0), S - 1);

    int o00 = yc0 * S + xc0;
    int o01 = yc0 * S + xc1;
    int o10 = yc1 * S + xc0;
    int o11 = yc1 * S + xc1;

    const float* img = x   + (size_t)b * CC * S * S;
    float*       op  = out + (size_t)b * CC * S * S + (size_t)y * S + xcol;

    #pragma unroll
    for (int c = 0; c < CC; c++) {
        const float* im = img + (size_t)c * S * S;
        float v = w00 * __ldg(im + o00) + w01 * __ldg(im + o01)
                + w10 * __ldg(im + o10) + w11 * __ldg(im + o11);
        op[(size_t)c * S * S] = v;
    }
}

extern "C" void kernel_launch(void* const* d_in, const int* in_sizes, int n_in,
                              void* d_out, int out_size)
{
    const float* x  = (const float*)d_in[0];
    const float* ox = (const float*)d_in[1];
    const float* oy = (const float*)d_in[2];
    const float* w  = (const float*)d_in[3];
    const int*   mm = (const int*)  d_in[4];

    smooth_kernel<<<BB * 2, 128>>>(ox, oy, w, mm);

    dim3 blk(256, 1, 1);
    dim3 grd(S / 256, S, BB);
    deform_kernel<<<grd, blk>>>(x, (float*)d_out);
}

// round 5
// speedup vs baseline: 1.0753x; 1.0753x over previous
#include <cuda_runtime.h>

#define S 1024
#define G 10
#define F 5
#define BB 8
#define CC 3
#define KW (2*F+1)
#define PX 4          // pixels per thread (x direction)
#define TPB 128       // threads per block

// Scratch for the smoothed, clipped offset field: (B, 2, G, G)
__device__ float g_smooth_dev[BB * 2 * G * G];

// ---------------------------------------------------------------------------
// Kernel 1: 11x11 edge-padded conv of the 10x10 offset fields + clip.
// ---------------------------------------------------------------------------
__global__ void smooth_kernel(const float* __restrict__ ox,
                              const float* __restrict__ oy,
                              const float* __restrict__ w,
                              const int*   __restrict__ mm_raw)
{
    int   mi = mm_raw[0];
    float max_move = (mi > 0 && mi < 1000000) ? (float)mi : __int_as_float(mi);
    float max_offset = 2.0f * max_move / (float)S;

    __shared__ float sw[KW * KW];
    __shared__ float so[G * G];

    int b  = blockIdx.x >> 1;
    int ch = blockIdx.x & 1;
    const float* o = (ch == 0 ? ox : oy) + b * G * G;

    for (int i = threadIdx.x; i < KW * KW; i += blockDim.x) sw[i] = w[i];
    for (int i = threadIdx.x; i < G * G;   i += blockDim.x) so[i] = o[i];
    __syncthreads();

    for (int idx = threadIdx.x; idx < G * G; idx += blockDim.x) {
        int i = idx / G, j = idx % G;
        float acc = 0.0f;
        #pragma unroll
        for (int ky = 0; ky < KW; ky++) {
            int yy = min(max(i + ky - F, 0), G - 1);
            #pragma unroll
            for (int kx = 0; kx < KW; kx++) {
                int xx = min(max(j + kx - F, 0), G - 1);
                acc += so[yy * G + xx] * sw[ky * KW + kx];
            }
        }
        acc *= max_offset;
        acc = fminf(fmaxf(acc, -max_offset), max_offset);
        g_smooth_dev[(b * 2 + ch) * G * G + idx] = acc;
    }
}

// ---------------------------------------------------------------------------
// Kernel 2: fused upsample + grid build + bilinear grid_sample, 3 channels.
// y is fixed per block -> y-lerp of the 10x10 field hoisted to shared memory.
// Each thread computes PX consecutive x pixels, stores float4 per channel.
// ---------------------------------------------------------------------------
__global__ __launch_bounds__(TPB)
void deform_kernel(const float* __restrict__ x, float* __restrict__ out)
{
    const int b = blockIdx.z;
    const int y = blockIdx.y;

    __shared__ float rowg[2 * G];   // rowg[0..9] = gx row, rowg[10..19] = gy row

    const float scale = (float)G / (float)S;      // exact
    const float hs    = 0.5f * scale - 0.5f;

    // y-direction field interpolation, once per block
    if (threadIdx.x < 2 * G) {
        int ch = threadIdx.x / G;           // 0 = x field, 1 = y field
        int j  = threadIdx.x - ch * G;
        float sy  = fmaxf(fmaf((float)y, scale, hs), 0.0f);
        int   iy0 = min((int)sy, G - 1);
        int   iy1 = min(iy0 + 1, G - 1);
        float wy  = sy - (float)iy0;
        const float* f = g_smooth_dev + (b * 2 + ch) * G * G;
        float a = f[iy0 * G + j];
        float c = f[iy1 * G + j];
        rowg[threadIdx.x] = fmaf(c - a, wy, a);
    }
    __syncthreads();

    const float* rowgx = rowg;
    const float* rowgy = rowg + G;

    const int xbase = (blockIdx.x * TPB + threadIdx.x) * PX;
    const float pxs = 2.0f / (float)(S - 1);

    const float* img = x   + (size_t)b * CC * S * S;
    float*       op  = out + (size_t)b * CC * S * S + (size_t)y * S + xbase;

    float r[CC][PX];

    #pragma unroll
    for (int p = 0; p < PX; p++) {
        float xf = (float)(xbase + p);

        // field x-lerp from shared row
        float sx = fmaxf(fmaf(xf, scale, hs), 0.0f);
        int   j0 = min((int)sx, G - 1);
        int   j1 = min(j0 + 1, G - 1);
        float wx = sx - (float)j0;
        float ax0 = rowgx[j0], ax1 = rowgx[j1];
        float ay0 = rowgy[j0], ay1 = rowgy[j1];
        float gx = fmaf(ax1 - ax0, wx, ax0);
        float gy = fmaf(ay1 - ay0, wx, ay0);

        // identity grid + clip
        float g0 = fminf(fmaxf(gx + fmaf(xf, pxs, -1.0f), -1.0f), 1.0f);
        float g1 = fminf(fmaxf(gy + fmaf((float)y, pxs, -1.0f), -1.0f), 1.0f);

        // source coords: ((g+1)*S-1)/2 = g*512 + 511.5, in [-0.5, 1023.5]
        float ixf = fmaf(g0, 512.0f, 511.5f);
        float iyf = fmaf(g1, 512.0f, 511.5f);

        float fx = floorf(ixf), fy = floorf(iyf);
        int x0 = (int)fx, y0 = (int)fy;      // x0,y0 in [-1, 1023]
        float axx = ixf - fx, ayy = iyf - fy;
        float omx = 1.0f - axx, omy = 1.0f - ayy;

        // only-reachable boundary masks
        float mx0 = (x0 >= 0)     ? 1.0f : 0.0f;
        float mx1 = (x0 < S - 1)  ? 1.0f : 0.0f;   // x1 < S
        float my0 = (y0 >= 0)     ? 1.0f : 0.0f;
        float my1 = (y0 < S - 1)  ? 1.0f : 0.0f;

        float w00 = omy * omx * (my0 * mx0);
        float w01 = omy * axx * (my0 * mx1);
        float w10 = ayy * omx * (my1 * mx0);
        float w11 = ayy * axx * (my1 * mx1);

        int xc0 = max(x0, 0);
        int xc1 = min(x0 + 1, S - 1);
        int yc0 = max(y0, 0) << 10;          // *S
        int yc1 = min(y0 + 1, S - 1) << 10;

        int o00 = yc0 + xc0, o01 = yc0 + xc1;
        int o10 = yc1 + xc0, o11 = yc1 + xc1;

        #pragma unroll
        for (int c = 0; c < CC; c++) {
            const float* im = img + (size_t)c * S * S;
            r[c][p] = w00 * __ldg(im + o00) + w01 * __ldg(im + o01)
                    + w10 * __ldg(im + o10) + w11 * __ldg(im + o11);
        }
    }

    #pragma unroll
    for (int c = 0; c < CC; c++) {
        float4 v = make_float4(r[c][0], r[c][1], r[c][2], r[c][3]);
        *reinterpret_cast<float4*>(op + (size_t)c * S * S) = v;
    }
}

extern "C" void kernel_launch(void* const* d_in, const int* in_sizes, int n_in,
                              void* d_out, int out_size)
{
    const float* x  = (const float*)d_in[0];
    const float* ox = (const float*)d_in[1];
    const float* oy = (const float*)d_in[2];
    const float* w  = (const float*)d_in[3];
    const int*   mm = (const int*)  d_in[4];

    smooth_kernel<<<BB * 2, 128>>>(ox, oy, w, mm);

    dim3 blk(TPB, 1, 1);
    dim3 grd(S / (TPB * PX), S, BB);   // 2 x 1024 x 8
    deform_kernel<<<grd, blk>>>(x, (float*)d_out);
}

// round 7
// speedup vs baseline: 1.3287x; 1.2356x over previous
#include <cuda_runtime.h>

#define S 1024
#define G 10
#define F 5
#define BB 8
#define CC 3
#define KW (2*F+1)
#define PX 4          // pixels per thread (x direction), lane-strided
#define TPB 128       // threads per block
#define SPAN (PX*TPB) // 512 output pixels per block row-segment

// Scratch for the smoothed, clipped offset field: (B, 2, G, G)
__device__ float g_smooth_dev[BB * 2 * G * G];

// ---------------------------------------------------------------------------
// Kernel 1: 11x11 edge-padded conv of the 10x10 offset fields + clip.
// ---------------------------------------------------------------------------
__global__ void smooth_kernel(const float* __restrict__ ox,
                              const float* __restrict__ oy,
                              const float* __restrict__ w,
                              const int*   __restrict__ mm_raw)
{
    int   mi = mm_raw[0];
    float max_move = (mi > 0 && mi < 1000000) ? (float)mi : __int_as_float(mi);
    float max_offset = 2.0f * max_move / (float)S;

    __shared__ float sw[KW * KW];
    __shared__ float so[G * G];

    int b  = blockIdx.x >> 1;
    int ch = blockIdx.x & 1;
    const float* o = (ch == 0 ? ox : oy) + b * G * G;

    for (int i = threadIdx.x; i < KW * KW; i += blockDim.x) sw[i] = w[i];
    for (int i = threadIdx.x; i < G * G;   i += blockDim.x) so[i] = o[i];
    __syncthreads();

    for (int idx = threadIdx.x; idx < G * G; idx += blockDim.x) {
        int i = idx / G, j = idx % G;
        float acc = 0.0f;
        #pragma unroll
        for (int ky = 0; ky < KW; ky++) {
            int yy = min(max(i + ky - F, 0), G - 1);
            #pragma unroll
            for (int kx = 0; kx < KW; kx++) {
                int xx = min(max(j + kx - F, 0), G - 1);
                acc += so[yy * G + xx] * sw[ky * KW + kx];
            }
        }
        acc *= max_offset;
        acc = fminf(fmaxf(acc, -max_offset), max_offset);
        g_smooth_dev[(b * 2 + ch) * G * G + idx] = acc;
    }
}

// ---------------------------------------------------------------------------
// Kernel 2: fused upsample + grid build + bilinear grid_sample, 3 channels.
// y fixed per block; y-lerp of the field hoisted to shared memory.
// Lane-contiguous pixel mapping: thread tid handles x = xb + tid + p*TPB,
// so every gather LDG has a ~128B warp footprint (1-2 lines, not 4-5).
// ---------------------------------------------------------------------------
__global__ __launch_bounds__(TPB)
void deform_kernel(const float* __restrict__ x, float* __restrict__ out)
{
    const int b = blockIdx.z;
    const int y = blockIdx.y;

    __shared__ float rowg[2 * G];   // [0..9] = gx row, [10..19] = gy row

    const float scale = (float)G / (float)S;      // exact
    const float hs    = 0.5f * scale - 0.5f;

    // y-direction field interpolation, once per block
    if (threadIdx.x < 2 * G) {
        int ch = threadIdx.x / G;
        int j  = threadIdx.x - ch * G;
        float sy  = fmaxf(fmaf((float)y, scale, hs), 0.0f);
        int   iy0 = min((int)sy, G - 1);
        int   iy1 = min(iy0 + 1, G - 1);
        float wy  = sy - (float)iy0;
        const float* f = g_smooth_dev + (b * 2 + ch) * G * G;
        float a = f[iy0 * G + j];
        float c = f[iy1 * G + j];
        rowg[threadIdx.x] = fmaf(c - a, wy, a);
    }
    __syncthreads();

    const float* rowgx = rowg;
    const float* rowgy = rowg + G;

    const int xb  = blockIdx.x * SPAN;            // 0 or 512
    const float pxs = 2.0f / (float)(S - 1);
    const float pyv = fmaf((float)y, pxs, -1.0f); // identity grid y (const per block)

    const float* img = x   + (size_t)b * CC * S * S;
    float*       op  = out + (size_t)b * CC * S * S + (size_t)y * S
                           + xb + threadIdx.x;

    float r[CC][PX];

    #pragma unroll
    for (int p = 0; p < PX; p++) {
        float xf = (float)(xb + p * TPB + threadIdx.x);

        // field x-lerp from shared row
        float sx = fmaxf(fmaf(xf, scale, hs), 0.0f);
        int   j0 = min((int)sx, G - 1);
        int   j1 = min(j0 + 1, G - 1);
        float wx = sx - (float)j0;
        float ax0 = rowgx[j0], ax1 = rowgx[j1];
        float ay0 = rowgy[j0], ay1 = rowgy[j1];
        float gx = fmaf(ax1 - ax0, wx, ax0);
        float gy = fmaf(ay1 - ay0, wx, ay0);

        // identity grid + clip
        float g0 = fminf(fmaxf(gx + fmaf(xf, pxs, -1.0f), -1.0f), 1.0f);
        float g1 = fminf(fmaxf(gy + pyv, -1.0f), 1.0f);

        // source coords: ((g+1)*S-1)/2 = g*512 + 511.5, in [-0.5, 1023.5]
        float ixf = fmaf(g0, 512.0f, 511.5f);
        float iyf = fmaf(g1, 512.0f, 511.5f);

        float fx = floorf(ixf), fy = floorf(iyf);
        int x0 = (int)fx, y0 = (int)fy;      // in [-1, 1023]
        float axx = ixf - fx, ayy = iyf - fy;
        float omx = 1.0f - axx, omy = 1.0f - ayy;

        // only-reachable boundary masks
        float mx0 = (x0 >= 0)    ? 1.0f : 0.0f;
        float mx1 = (x0 < S - 1) ? 1.0f : 0.0f;
        float my0 = (y0 >= 0)    ? 1.0f : 0.0f;
        float my1 = (y0 < S - 1) ? 1.0f : 0.0f;

        float w00 = omy * omx * (my0 * mx0);
        float w01 = omy * axx * (my0 * mx1);
        float w10 = ayy * omx * (my1 * mx0);
        float w11 = ayy * axx * (my1 * mx1);

        int xc0 = max(x0, 0);
        int xc1 = min(x0 + 1, S - 1);
        int yc0 = max(y0, 0) << 10;          // *S
        int yc1 = min(y0 + 1, S - 1) << 10;

        int o00 = yc0 + xc0, o01 = yc0 + xc1;
        int o10 = yc1 + xc0, o11 = yc1 + xc1;

        #pragma unroll
        for (int c = 0; c < CC; c++) {
            const float* im = img + (size_t)c * S * S;
            r[c][p] = w00 * __ldg(im + o00) + w01 * __ldg(im + o01)
                    + w10 * __ldg(im + o10) + w11 * __ldg(im + o11);
        }
    }

    // Coalesced scalar stores: warp footprint = 128B per store instruction.
    #pragma unroll
    for (int c = 0; c < CC; c++) {
        float* oc = op + (size_t)c * S * S;
        #pragma unroll
        for (int p = 0; p < PX; p++)
            oc[p * TPB] = r[c][p];
    }
}

extern "C" void kernel_launch(void* const* d_in, const int* in_sizes, int n_in,
                              void* d_out, int out_size)
{
    const float* x  = (const float*)d_in[0];
    const float* ox = (const float*)d_in[1];
    const float* oy = (const float*)d_in[2];
    const float* w  = (const float*)d_in[3];
    const int*   mm = (const int*)  d_in[4];

    smooth_kernel<<<BB * 2, 128>>>(ox, oy, w, mm);

    dim3 blk(TPB, 1, 1);
    dim3 grd(S / SPAN, S, BB);   // 2 x 1024 x 8
    deform_kernel<<<grd, blk>>>(x, (float*)d_out);
}